// round 2
// baseline (speedup 1.0000x reference)
#include <cuda_runtime.h>

#define ROWS 4096
#define COLS 6144
#define VEC_PER_ROW (COLS / 4)      // 1536 float4 per row
#define PHI_VEC     (4096 / 4)      // 1024 float4 cover cols [0,4096)
#define THREADS 256
#define NWARPS (THREADS / 32)

// Per-row partial sums (scratch; no allocation allowed in kernel_launch).
__device__ float g_rt[ROWS];            // r-sum (row%3==0) or theta-sum (row%3==1); 0 for row%3==2
__device__ float g_phi[ROWS];           // phi-sum for every row
__device__ unsigned int g_count = 0;    // arrival counter for last-block finalize

__device__ __forceinline__ float sigmoidf(float x) {
    return __fdividef(1.0f, 1.0f + __expf(-x));
}

__device__ __forceinline__ float block_reduce2(float v, float* sh) {
#pragma unroll
    for (int o = 16; o > 0; o >>= 1) v += __shfl_down_sync(0xFFFFFFFFu, v, o);
    const int lane = threadIdx.x & 31;
    const int warp = threadIdx.x >> 5;
    if (lane == 0) sh[warp] = v;
    __syncthreads();
    v = (threadIdx.x < NWARPS) ? sh[threadIdx.x] : 0.0f;
    if (warp == 0) {
#pragma unroll
        for (int o = NWARPS / 2; o > 0; o >>= 1) v += __shfl_down_sync(0xFFFFFFFFu, v, o);
    }
    return v;  // valid in lane 0 of warp 0
}

__global__ void __launch_bounds__(THREADS)
spherical_fused(const float* __restrict__ preds, const float* __restrict__ targs,
                float* __restrict__ out) {
    const int r = blockIdx.x;
    const int rowmod = r % 3;
    const float4* __restrict__ p4 = (const float4*)(preds + (size_t)r * COLS);
    const float4* __restrict__ t4 = (const float4*)(targs + (size_t)r * COLS);

    // rows ==2 mod 3 contribute only phi, which lives in cols [0,4096)
    const int nvec = (rowmod == 2) ? PHI_VEC : VEC_PER_ROW;

    float srt = 0.0f;
    float sphi = 0.0f;

    for (int i = threadIdx.x; i < nvec; i += THREADS) {
        float4 p = p4[i];
        float4 t = t4[i];
        const int c0 = 4 * i;
        float pv[4] = {p.x, p.y, p.z, p.w};
        float tv[4] = {t.x, t.y, t.z, t.w};
#pragma unroll
        for (int j = 0; j < 4; j++) {
            const int c = c0 + j;
            float s  = sigmoidf(pv[j]);
            float ad = fabsf(s - tv[j]);
            if (rowmod < 2) srt += ad;
            if (c < 4096 && (c % 3) == 2) sphi += fminf(ad, 1.0f - ad);
        }
    }

    __shared__ float sh_a[NWARPS];
    __shared__ float sh_b[NWARPS];
    float tot_rt  = block_reduce2(srt, sh_a);
    __syncthreads();
    float tot_phi = block_reduce2(sphi, sh_b);

    // One thread publishes this block's partials, then arrives on the counter.
    __shared__ bool s_last;
    if (threadIdx.x == 0) {
        g_rt[r]  = tot_rt;
        g_phi[r] = tot_phi;
        __threadfence();
        unsigned int prev = atomicAdd(&g_count, 1u);
        s_last = (prev == (unsigned int)(ROWS - 1));
    }
    __syncthreads();

    if (!s_last) return;

    // ---- Last-arriving block finalizes (deterministic: fixed read/sum order) ----
    float rs = 0.0f, ts = 0.0f, ps = 0.0f;
    for (int i = threadIdx.x; i < ROWS; i += THREADS) {
        float v = g_rt[i];
        int m = i % 3;
        if (m == 0)      rs += v;
        else if (m == 1) ts += v;
        ps += g_phi[i];
    }

    __shared__ float sh3[3][NWARPS];
#pragma unroll
    for (int o = 16; o > 0; o >>= 1) {
        rs += __shfl_down_sync(0xFFFFFFFFu, rs, o);
        ts += __shfl_down_sync(0xFFFFFFFFu, ts, o);
        ps += __shfl_down_sync(0xFFFFFFFFu, ps, o);
    }
    const int lane = threadIdx.x & 31;
    const int warp = threadIdx.x >> 5;
    if (lane == 0) { sh3[0][warp] = rs; sh3[1][warp] = ts; sh3[2][warp] = ps; }
    __syncthreads();
    if (warp == 0) {
        rs = (lane < NWARPS) ? sh3[0][lane] : 0.0f;
        ts = (lane < NWARPS) ? sh3[1][lane] : 0.0f;
        ps = (lane < NWARPS) ? sh3[2][lane] : 0.0f;
#pragma unroll
        for (int o = NWARPS / 2; o > 0; o >>= 1) {
            rs += __shfl_down_sync(0xFFFFFFFFu, rs, o);
            ts += __shfl_down_sync(0xFFFFFFFFu, ts, o);
            ps += __shfl_down_sync(0xFFFFFFFFu, ps, o);
        }
        if (lane == 0) {
            float r_loss   = rs / (1366.0f * 6144.0f);
            float t_loss   = ts / (1365.0f * 6144.0f);
            float phi_loss = ps / (4096.0f * 2048.0f);
            out[0] = r_loss + t_loss + phi_loss;
            out[1] = r_loss;
            out[2] = t_loss;
            out[3] = phi_loss;
            g_count = 0;   // reset for next graph replay (deterministic re-run)
        }
    }
}

extern "C" void kernel_launch(void* const* d_in, const int* in_sizes, int n_in,
                              void* d_out, int out_size) {
    const float* preds = (const float*)d_in[0];
    const float* targs = (const float*)d_in[1];
    float* out = (float*)d_out;
    (void)in_sizes; (void)n_in; (void)out_size;

    spherical_fused<<<ROWS, THREADS>>>(preds, targs, out);
}

// round 3
// speedup vs baseline: 1.1449x; 1.1449x over previous
#include <cuda_runtime.h>

#define ROWS 4096
#define COLS 6144
#define NTILES 512              // 6144 / 12 column-tiles per row
#define PHI_TILE_FULL 341       // tiles 0..340 fully below col 4096
// tile 341: cols 4092..4103; only col 4094 (f4#0, j=2) is a valid phi col (<4096)
#define THREADS 256
#define NWARPS (THREADS / 32)

// Scratch partials (no allocation allowed in kernel_launch)
__device__ float g_r[1366];     // rows 0,3,...,4095
__device__ float g_t[1365];     // rows 1,4,...,4093
__device__ float g_phi[ROWS];   // every row

__device__ __forceinline__ float sigmoidf(float x) {
    return __fdividef(1.0f, 1.0f + __expf(-x));
}
__device__ __forceinline__ float circd(float ad) {   // ad = |s - t|, both in (0,1)
    return fminf(ad, 1.0f - ad);
}

__device__ __forceinline__ void block_reduce_pair(float a, float b, float* outA, float* outB) {
    __shared__ float shA[NWARPS], shB[NWARPS];
#pragma unroll
    for (int o = 16; o > 0; o >>= 1) {
        a += __shfl_down_sync(0xFFFFFFFFu, a, o);
        b += __shfl_down_sync(0xFFFFFFFFu, b, o);
    }
    const int lane = threadIdx.x & 31;
    const int warp = threadIdx.x >> 5;
    if (lane == 0) { shA[warp] = a; shB[warp] = b; }
    __syncthreads();
    if (warp == 0) {
        a = (lane < NWARPS) ? shA[lane] : 0.0f;
        b = (lane < NWARPS) ? shB[lane] : 0.0f;
#pragma unroll
        for (int o = NWARPS / 2; o > 0; o >>= 1) {
            a += __shfl_down_sync(0xFFFFFFFFu, a, o);
            b += __shfl_down_sync(0xFFFFFFFFu, b, o);
        }
        if (lane == 0) { *outA = a; *outB = b; }
    }
}

__global__ void __launch_bounds__(THREADS)
spherical_pass1(const float* __restrict__ preds, const float* __restrict__ targs) {
    const int r = blockIdx.x;
    const int rowmod = r % 3;
    const bool wantRT = (rowmod < 2);
    const float4* __restrict__ p4 = (const float4*)(preds + (size_t)r * COLS);
    const float4* __restrict__ t4 = (const float4*)(targs + (size_t)r * COLS);

    // phi-only rows need tiles covering cols < 4096 only
    const int ntiles = wantRT ? NTILES : (PHI_TILE_FULL + 1);

    float srt = 0.0f, sphi = 0.0f;

    for (int k = threadIdx.x; k < ntiles; k += THREADS) {
        const int i0 = 3 * k;                    // first float4 of this 12-col tile
        float4 pa = p4[i0],     ta = t4[i0];
        float4 pb = p4[i0 + 1], tb = t4[i0 + 1];
        float4 pc = p4[i0 + 2], tc = t4[i0 + 2];

        // |sigmoid(p) - t| for all 12 elements
        float a0 = fabsf(sigmoidf(pa.x) - ta.x);
        float a1 = fabsf(sigmoidf(pa.y) - ta.y);
        float a2 = fabsf(sigmoidf(pa.z) - ta.z);   // col 12k+2  (phi if k<=341)
        float a3 = fabsf(sigmoidf(pa.w) - ta.w);
        float b0 = fabsf(sigmoidf(pb.x) - tb.x);
        float b1 = fabsf(sigmoidf(pb.y) - tb.y);   // col 12k+5  (phi if k<341)
        float b2 = fabsf(sigmoidf(pb.z) - tb.z);
        float b3 = fabsf(sigmoidf(pb.w) - tb.w);
        float c0 = fabsf(sigmoidf(pc.x) - tc.x);   // col 12k+8  (phi if k<341)
        float c1 = fabsf(sigmoidf(pc.y) - tc.y);
        float c2 = fabsf(sigmoidf(pc.z) - tc.z);
        float c3 = fabsf(sigmoidf(pc.w) - tc.w);   // col 12k+11 (phi if k<341)

        if (wantRT)
            srt += ((a0 + a1) + (a2 + a3)) + ((b0 + b1) + (b2 + b3)) + ((c0 + c1) + (c2 + c3));

        if (k <= PHI_TILE_FULL) {
            float ph = circd(a2);
            if (k < PHI_TILE_FULL)
                ph += circd(b1) + circd(c0) + circd(c3);
            sphi += ph;
        }
    }

    __shared__ float s_rt, s_phi;
    block_reduce_pair(srt, sphi, &s_rt, &s_phi);
    __syncthreads();

    if (threadIdx.x == 0) {
        if (rowmod == 0)      g_r[r / 3] = s_rt;
        else if (rowmod == 1) g_t[r / 3] = s_rt;
        g_phi[r] = s_phi;
    }
}

__global__ void __launch_bounds__(THREADS)
spherical_pass2(float* __restrict__ out) {
    float rs = 0.0f, ts = 0.0f, ps = 0.0f;
    for (int i = threadIdx.x; i < 1366; i += THREADS) rs += g_r[i];
    for (int i = threadIdx.x; i < 1365; i += THREADS) ts += g_t[i];
    const float4* phi4 = (const float4*)g_phi;     // 1024 float4
    for (int i = threadIdx.x; i < ROWS / 4; i += THREADS) {
        float4 v = phi4[i];
        ps += (v.x + v.y) + (v.z + v.w);
    }

    __shared__ float sh[3][NWARPS];
#pragma unroll
    for (int o = 16; o > 0; o >>= 1) {
        rs += __shfl_down_sync(0xFFFFFFFFu, rs, o);
        ts += __shfl_down_sync(0xFFFFFFFFu, ts, o);
        ps += __shfl_down_sync(0xFFFFFFFFu, ps, o);
    }
    const int lane = threadIdx.x & 31;
    const int warp = threadIdx.x >> 5;
    if (lane == 0) { sh[0][warp] = rs; sh[1][warp] = ts; sh[2][warp] = ps; }
    __syncthreads();
    if (warp == 0) {
        rs = (lane < NWARPS) ? sh[0][lane] : 0.0f;
        ts = (lane < NWARPS) ? sh[1][lane] : 0.0f;
        ps = (lane < NWARPS) ? sh[2][lane] : 0.0f;
#pragma unroll
        for (int o = NWARPS / 2; o > 0; o >>= 1) {
            rs += __shfl_down_sync(0xFFFFFFFFu, rs, o);
            ts += __shfl_down_sync(0xFFFFFFFFu, ts, o);
            ps += __shfl_down_sync(0xFFFFFFFFu, ps, o);
        }
        if (lane == 0) {
            float r_loss   = rs / (1366.0f * 6144.0f);
            float t_loss   = ts / (1365.0f * 6144.0f);
            float phi_loss = ps / (4096.0f * 2048.0f);
            out[0] = r_loss + t_loss + phi_loss;
            out[1] = r_loss;
            out[2] = t_loss;
            out[3] = phi_loss;
        }
    }
}

extern "C" void kernel_launch(void* const* d_in, const int* in_sizes, int n_in,
                              void* d_out, int out_size) {
    const float* preds = (const float*)d_in[0];
    const float* targs = (const float*)d_in[1];
    float* out = (float*)d_out;
    (void)in_sizes; (void)n_in; (void)out_size;

    spherical_pass1<<<ROWS, THREADS>>>(preds, targs);
    spherical_pass2<<<1, THREADS>>>(out);
}

// round 4
// speedup vs baseline: 1.1635x; 1.0163x over previous
#include <cuda_runtime.h>

#define ROWS 4096
#define COLS 6144
#define NTILES 512              // 6144 / 12 column-tiles per row
#define PHI_TILE_FULL 341       // tiles 0..340 fully below col 4096
// tile 341: cols 4092..4103; only col 4094 (f4#0, j=2) is a valid phi col (<4096)
#define THREADS 256
#define NWARPS (THREADS / 32)

// Scratch partials (no allocation allowed in kernel_launch)
__device__ float g_r[1366];     // rows 0,3,...,4095
__device__ float g_t[1365];     // rows 1,4,...,4093
__device__ float g_phi[ROWS];   // every row

__device__ __forceinline__ float sigmoidf(float x) {
    return __fdividef(1.0f, 1.0f + __expf(-x));
}
__device__ __forceinline__ float circd(float ad) {   // ad = |s - t|, both in (0,1)
    return fminf(ad, 1.0f - ad);
}

__device__ __forceinline__ void block_reduce_pair(float a, float b, float* outA, float* outB) {
    __shared__ float shA[NWARPS], shB[NWARPS];
#pragma unroll
    for (int o = 16; o > 0; o >>= 1) {
        a += __shfl_down_sync(0xFFFFFFFFu, a, o);
        b += __shfl_down_sync(0xFFFFFFFFu, b, o);
    }
    const int lane = threadIdx.x & 31;
    const int warp = threadIdx.x >> 5;
    if (lane == 0) { shA[warp] = a; shB[warp] = b; }
    __syncthreads();
    if (warp == 0) {
        a = (lane < NWARPS) ? shA[lane] : 0.0f;
        b = (lane < NWARPS) ? shB[lane] : 0.0f;
#pragma unroll
        for (int o = NWARPS / 2; o > 0; o >>= 1) {
            a += __shfl_down_sync(0xFFFFFFFFu, a, o);
            b += __shfl_down_sync(0xFFFFFFFFu, b, o);
        }
        if (lane == 0) { *outA = a; *outB = b; }
    }
}

__global__ void __launch_bounds__(THREADS)
spherical_pass1(const float* __restrict__ preds, const float* __restrict__ targs) {
    const int r = blockIdx.x;
    const int rowmod = r % 3;
    const bool wantRT = (rowmod < 2);
    const float4* __restrict__ p4 = (const float4*)(preds + (size_t)r * COLS);
    const float4* __restrict__ t4 = (const float4*)(targs + (size_t)r * COLS);

    // phi-only rows need tiles covering cols < 4096 only
    const int ntiles = wantRT ? NTILES : (PHI_TILE_FULL + 1);

    float srt = 0.0f, sphi = 0.0f;

    for (int k = threadIdx.x; k < ntiles; k += THREADS) {
        const int i0 = 3 * k;                    // first float4 of this 12-col tile
        float4 pa = p4[i0],     ta = t4[i0];
        float4 pb = p4[i0 + 1], tb = t4[i0 + 1];
        float4 pc = p4[i0 + 2], tc = t4[i0 + 2];

        // |sigmoid(p) - t| for all 12 elements
        float a0 = fabsf(sigmoidf(pa.x) - ta.x);
        float a1 = fabsf(sigmoidf(pa.y) - ta.y);
        float a2 = fabsf(sigmoidf(pa.z) - ta.z);   // col 12k+2  (phi if k<=341)
        float a3 = fabsf(sigmoidf(pa.w) - ta.w);
        float b0 = fabsf(sigmoidf(pb.x) - tb.x);
        float b1 = fabsf(sigmoidf(pb.y) - tb.y);   // col 12k+5  (phi if k<341)
        float b2 = fabsf(sigmoidf(pb.z) - tb.z);
        float b3 = fabsf(sigmoidf(pb.w) - tb.w);
        float c0 = fabsf(sigmoidf(pc.x) - tc.x);   // col 12k+8  (phi if k<341)
        float c1 = fabsf(sigmoidf(pc.y) - tc.y);
        float c2 = fabsf(sigmoidf(pc.z) - tc.z);
        float c3 = fabsf(sigmoidf(pc.w) - tc.w);   // col 12k+11 (phi if k<341)

        if (wantRT)
            srt += ((a0 + a1) + (a2 + a3)) + ((b0 + b1) + (b2 + b3)) + ((c0 + c1) + (c2 + c3));

        if (k <= PHI_TILE_FULL) {
            float ph = circd(a2);
            if (k < PHI_TILE_FULL)
                ph += circd(b1) + circd(c0) + circd(c3);
            sphi += ph;
        }
    }

    __shared__ float s_rt, s_phi;
    block_reduce_pair(srt, sphi, &s_rt, &s_phi);
    __syncthreads();

    if (threadIdx.x == 0) {
        if (rowmod == 0)      g_r[r / 3] = s_rt;
        else if (rowmod == 1) g_t[r / 3] = s_rt;
        g_phi[r] = s_phi;
    }
}

__global__ void __launch_bounds__(THREADS)
spherical_pass2(float* __restrict__ out) {
    float rs = 0.0f, ts = 0.0f, ps = 0.0f;
    for (int i = threadIdx.x; i < 1366; i += THREADS) rs += g_r[i];
    for (int i = threadIdx.x; i < 1365; i += THREADS) ts += g_t[i];
    const float4* phi4 = (const float4*)g_phi;     // 1024 float4
    for (int i = threadIdx.x; i < ROWS / 4; i += THREADS) {
        float4 v = phi4[i];
        ps += (v.x + v.y) + (v.z + v.w);
    }

    __shared__ float sh[3][NWARPS];
#pragma unroll
    for (int o = 16; o > 0; o >>= 1) {
        rs += __shfl_down_sync(0xFFFFFFFFu, rs, o);
        ts += __shfl_down_sync(0xFFFFFFFFu, ts, o);
        ps += __shfl_down_sync(0xFFFFFFFFu, ps, o);
    }
    const int lane = threadIdx.x & 31;
    const int warp = threadIdx.x >> 5;
    if (lane == 0) { sh[0][warp] = rs; sh[1][warp] = ts; sh[2][warp] = ps; }
    __syncthreads();
    if (warp == 0) {
        rs = (lane < NWARPS) ? sh[0][lane] : 0.0f;
        ts = (lane < NWARPS) ? sh[1][lane] : 0.0f;
        ps = (lane < NWARPS) ? sh[2][lane] : 0.0f;
#pragma unroll
        for (int o = NWARPS / 2; o > 0; o >>= 1) {
            rs += __shfl_down_sync(0xFFFFFFFFu, rs, o);
            ts += __shfl_down_sync(0xFFFFFFFFu, ts, o);
            ps += __shfl_down_sync(0xFFFFFFFFu, ps, o);
        }
        if (lane == 0) {
            float r_loss   = rs / (1366.0f * 6144.0f);
            float t_loss   = ts / (1365.0f * 6144.0f);
            float phi_loss = ps / (4096.0f * 2048.0f);
            out[0] = r_loss + t_loss + phi_loss;
            out[1] = r_loss;
            out[2] = t_loss;
            out[3] = phi_loss;
        }
    }
}

extern "C" void kernel_launch(void* const* d_in, const int* in_sizes, int n_in,
                              void* d_out, int out_size) {
    const float* preds = (const float*)d_in[0];
    const float* targs = (const float*)d_in[1];
    float* out = (float*)d_out;
    (void)in_sizes; (void)n_in; (void)out_size;

    spherical_pass1<<<ROWS, THREADS>>>(preds, targs);
    spherical_pass2<<<1, THREADS>>>(out);
}